// round 1
// baseline (speedup 1.0000x reference)
#include <cuda_runtime.h>
#include <cstdint>
#include <math.h>

// Problem constants (fixed by the dataset)
#define NF 64     // N_FIXED
#define Bn 5000   // batters
#define Ln 10     // leagues
#define Tn 25     // seasons
#define Kn 8      // outputs

// Scratch: u-table [t][b][l][k]  (40 MB) + cholesky diag d[l][k]
__device__ float g_u[(size_t)Tn * Bn * Ln * Kn];
__device__ float g_d[Ln * Kn];

// ---------------------------------------------------------------------------
// Kernel 0: cholesky diagonal of Sigma[k] (K matrices of LxL), d[l,k]=chol[l,l]
// ---------------------------------------------------------------------------
__global__ void chol_kernel(const float* __restrict__ Sigma) {
    int k = threadIdx.x;
    if (k >= Kn) return;
    float A[Ln][Ln];
    const float* S = Sigma + k * Ln * Ln;
    for (int i = 0; i < Ln; i++)
        for (int j = 0; j < Ln; j++)
            A[i][j] = S[i * Ln + j];
    for (int i = 0; i < Ln; i++) {
        for (int j = 0; j < i; j++) {
            float s = A[i][j];
            for (int p = 0; p < j; p++) s -= A[i][p] * A[j][p];
            A[i][j] = s / A[j][j];
        }
        float s = A[i][i];
        for (int p = 0; p < i; p++) s -= A[i][p] * A[i][p];
        float dii = sqrtf(s);
        A[i][i] = dii;
        g_d[i * Kn + k] = dii;
    }
}

// ---------------------------------------------------------------------------
// Kernel 1: AR(1) scan. One thread per (b,l,k) chain, serial over T=25.
//   u[0] = eps[b,l,0,k];  u[t] = rho*u[t-1] + d*eps[b,l,t,k]
// eps layout: [B][L][T][K]. u written as [t][b][l][k] so gather rows are 32B.
// ---------------------------------------------------------------------------
__global__ void scan_kernel(const float* __restrict__ eps,
                            const float* __restrict__ raw_rho) {
    int idx = blockIdx.x * blockDim.x + threadIdx.x;
    if (idx >= Bn * Ln * Kn) return;
    int k = idx & (Kn - 1);
    int l = (idx / Kn) % Ln;
    int b = idx / (Kn * Ln);

    float rho = tanhf(raw_rho[l * Kn + k]);
    float d   = g_d[l * Kn + k];

    const float* e = eps + ((size_t)(b * Ln + l) * Tn) * Kn + k;
    float* up = g_u + (size_t)(b * Ln + l) * Kn + k;   // t=0 slot
    const size_t ustep = (size_t)Bn * Ln * Kn;

    float u = e[0];
    up[0] = u;
#pragma unroll
    for (int t = 1; t < Tn; t++) {
        u = fmaf(rho, u, d * e[(size_t)t * Kn]);
        up[(size_t)t * ustep] = u;
    }
}

// ---------------------------------------------------------------------------
// Kernel 2: out[n,:] = X[n,:] @ beta + u[s,b,l,:]
// One thread per row. beta (64x8 = 2KB) staged in shared as f32x2 pairs,
// accumulated with packed fma.rn.f32x2 (2x FFMA throughput on sm_103a).
// ---------------------------------------------------------------------------
#define FMA2(d_, a_, b_, c_) \
    asm("fma.rn.f32x2 %0, %1, %2, %3;" : "=l"(d_) : "l"(a_), "l"(b_), "l"(c_))

__global__ void __launch_bounds__(256)
main_kernel(const float* __restrict__ X,
            const int* __restrict__ batter_ids,
            const int* __restrict__ league_ids,
            const int* __restrict__ season_ids,
            const float* __restrict__ beta,
            float* __restrict__ out, int N) {
    __shared__ unsigned long long sbeta[NF * Kn / 2];   // 256 pairs
    for (int i = threadIdx.x; i < NF * Kn / 2; i += blockDim.x)
        sbeta[i] = ((const unsigned long long*)beta)[i];
    __syncthreads();

    int n = blockIdx.x * blockDim.x + threadIdx.x;
    if (n >= N) return;

    unsigned long long acc0 = 0ull, acc1 = 0ull, acc2 = 0ull, acc3 = 0ull;

    const float4* xr = (const float4*)(X + (size_t)n * NF);
#pragma unroll
    for (int q = 0; q < NF / 4; q++) {
        float4 x = xr[q];
        float xs[4] = {x.x, x.y, x.z, x.w};
#pragma unroll
        for (int r = 0; r < 4; r++) {
            int j = q * 4 + r;
            unsigned int xb = __float_as_uint(xs[r]);
            unsigned long long xp;
            asm("mov.b64 %0, {%1,%2};" : "=l"(xp) : "r"(xb), "r"(xb));
            FMA2(acc0, xp, sbeta[j * 4 + 0], acc0);
            FMA2(acc1, xp, sbeta[j * 4 + 1], acc1);
            FMA2(acc2, xp, sbeta[j * 4 + 2], acc2);
            FMA2(acc3, xp, sbeta[j * 4 + 3], acc3);
        }
    }

    int s = season_ids[n], b = batter_ids[n], l = league_ids[n];
    const float4* up =
        (const float4*)(g_u + ((size_t)(s * Bn + b) * Ln + l) * Kn);
    float4 u0 = up[0];
    float4 u1 = up[1];

    float a0x, a0y, a1x, a1y, a2x, a2y, a3x, a3y;
    asm("mov.b64 {%0,%1}, %2;" : "=f"(a0x), "=f"(a0y) : "l"(acc0));
    asm("mov.b64 {%0,%1}, %2;" : "=f"(a1x), "=f"(a1y) : "l"(acc1));
    asm("mov.b64 {%0,%1}, %2;" : "=f"(a2x), "=f"(a2y) : "l"(acc2));
    asm("mov.b64 {%0,%1}, %2;" : "=f"(a3x), "=f"(a3y) : "l"(acc3));

    float4 o0 = make_float4(a0x + u0.x, a0y + u0.y, a1x + u0.z, a1y + u0.w);
    float4 o1 = make_float4(a2x + u1.x, a2y + u1.y, a3x + u1.z, a3y + u1.w);
    float4* op = (float4*)(out + (size_t)n * Kn);
    op[0] = o0;
    op[1] = o1;
}

// ---------------------------------------------------------------------------
// Launch: inputs in metadata order:
//   0:X  1:batter_ids  2:league_ids  3:season_ids  4:beta  5:raw_rho
//   6:Sigma  7:eps
// ---------------------------------------------------------------------------
extern "C" void kernel_launch(void* const* d_in, const int* in_sizes, int n_in,
                              void* d_out, int out_size) {
    const float* X        = (const float*)d_in[0];
    const int*   bid      = (const int*)d_in[1];
    const int*   lid      = (const int*)d_in[2];
    const int*   sid      = (const int*)d_in[3];
    const float* beta     = (const float*)d_in[4];
    const float* raw_rho  = (const float*)d_in[5];
    const float* Sigma    = (const float*)d_in[6];
    const float* eps      = (const float*)d_in[7];
    float*       out      = (float*)d_out;

    const int N = in_sizes[1];  // rows

    chol_kernel<<<1, 32>>>(Sigma);

    int chains = Bn * Ln * Kn;
    scan_kernel<<<(chains + 255) / 256, 256>>>(eps, raw_rho);

    main_kernel<<<(N + 255) / 256, 256>>>(X, bid, lid, sid, beta, out, N);
}